// round 3
// baseline (speedup 1.0000x reference)
#include <cuda_runtime.h>
#include <cuda_bf16.h>

// XORNet forward: 2-layer LIF spiking net (snntorch Leaky, subtract reset).
//   cur = x @ w1^T                      [B,4], timestep-invariant
//   per t: reset1 = (m1 > 1); m1 = 0.9*m1 + cur - reset1
//          spk1  = (m1 > 1)
//          out   = spk1 @ w2^T          (binary spk1 -> exact conditional adds)
//          reset2 = (m2 > 1); m2 = 0.9*m2 + out - reset2
//          spk2  = (m2 > 1)  -> output[t, b]
//
// HBM-bound: 8.4 MB read + 83.9 MB write. One thread per 4 batch elements,
// float4 loads/stores, fully-unrolled T=20 recurrence in registers.
//
// Numerics: explicit __f*_rn intrinsics forbid FFMA contraction in the
// membrane update (matches XLA's un-contracted elementwise mul/add); the
// layer-2 dot is order-preserving conditional adds (exact for binary spikes);
// cur uses fma(x1,w11, x0*w10) matching XLA's k-ascending fma dot.

#define SNN_T 20
#define SNN_H 4

__global__ __launch_bounds__(256) void xornet_snn_kernel(
    const float* __restrict__ x,    // [B, 2]
    const float* __restrict__ w1,   // [4, 2]
    const float* __restrict__ w2,   // [1, 4]
    float* __restrict__ out,        // [T, B, 1]
    int B)                          // batch size (multiple of 4)
{
    const int i = blockIdx.x * blockDim.x + threadIdx.x;  // handles b = 4i..4i+3
    const int b0 = i * 4;
    if (b0 >= B) return;
    const int Bq = B >> 2;  // B/4, float4 stride per timestep

    // Broadcast weights (L1/L2 hit for all but the first warp).
    float w1r0[SNN_H], w1r1[SNN_H], w2r[SNN_H];
#pragma unroll
    for (int h = 0; h < SNN_H; h++) {
        w1r0[h] = __ldg(&w1[2 * h]);
        w1r1[h] = __ldg(&w1[2 * h + 1]);
        w2r[h]  = __ldg(&w2[h]);
    }

    // x for 4 batch elements: 8 consecutive floats = 2x float4.
    const float4 xa = __ldg(&((const float4*)x)[2 * i]);
    const float4 xb = __ldg(&((const float4*)x)[2 * i + 1]);
    const float x0[4] = {xa.x, xa.z, xb.x, xb.z};
    const float x1[4] = {xa.y, xa.w, xb.y, xb.w};

    // cur[l][h] = fma(x1, w1[h][1], x0*w1[h][0])  (k-ascending fma dot)
    float cur[4][SNN_H];
#pragma unroll
    for (int l = 0; l < 4; l++)
#pragma unroll
        for (int h = 0; h < SNN_H; h++)
            cur[l][h] = fmaf(x1[l], w1r1[h], __fmul_rn(x0[l], w1r0[h]));

    float m1[4][SNN_H];
    float m2[4];
#pragma unroll
    for (int l = 0; l < 4; l++) {
        m2[l] = 0.0f;
#pragma unroll
        for (int h = 0; h < SNN_H; h++) m1[l][h] = 0.0f;
    }

#pragma unroll
    for (int t = 0; t < SNN_T; t++) {
        float sp[4];
#pragma unroll
        for (int l = 0; l < 4; l++) {
            float o = 0.0f;
#pragma unroll
            for (int h = 0; h < SNN_H; h++) {
                // reset from PREVIOUS membrane; (m-1 > 0) == (m > 1) exactly.
                const float r = (m1[l][h] > 1.0f) ? 1.0f : 0.0f;
                // m = 0.9*m + cur - r   (no FFMA contraction: match plain ops)
                float mm = __fmul_rn(0.9f, m1[l][h]);
                mm = __fadd_rn(mm, cur[l][h]);
                mm = __fsub_rn(mm, r);
                m1[l][h] = mm;
                // spk1 @ w2^T: binary weights -> exact, order-preserving adds
                if (mm > 1.0f) o = __fadd_rn(o, w2r[h]);
            }
            const float r2 = (m2[l] > 1.0f) ? 1.0f : 0.0f;
            float mm2 = __fmul_rn(0.9f, m2[l]);
            mm2 = __fadd_rn(mm2, o);
            mm2 = __fsub_rn(mm2, r2);
            m2[l] = mm2;
            sp[l] = (mm2 > 1.0f) ? 1.0f : 0.0f;
        }
        float4 ov;
        ov.x = sp[0]; ov.y = sp[1]; ov.z = sp[2]; ov.w = sp[3];
        ((float4*)out)[(size_t)t * Bq + i] = ov;  // warp-coalesced STG.128
    }
}

extern "C" void kernel_launch(void* const* d_in, const int* in_sizes, int n_in,
                              void* d_out, int out_size)
{
    const float* x  = (const float*)d_in[0];   // [B, 2]
    const float* w1 = (const float*)d_in[1];   // [4, 2]
    const float* w2 = (const float*)d_in[2];   // [1, 4]
    float* out = (float*)d_out;                // [T, B, 1]

    const int B = in_sizes[0] / 2;             // 1,048,576
    const int threads = 256;
    const int nthreads = B / 4;                // one thread per 4 batch elems
    const int blocks = (nthreads + threads - 1) / threads;

    xornet_snn_kernel<<<blocks, threads>>>(x, w1, w2, out, B);
}

// round 5
// speedup vs baseline: 1.3662x; 1.3662x over previous
#include <cuda_runtime.h>
#include <cuda_bf16.h>

// XORNet forward: 2-layer LIF spiking net (snntorch Leaky, subtract reset).
// R3 ncu: issue=86.7%, fma+alu ~93%, DRAM 18.7% -> ISSUE-SLOT bound, not HBM.
// R4 bench was an infra failure (container died); resubmitting unchanged to
// measure the R3->R4 change: ~30% fewer issue slots, bit-identical numerics:
//   - mul.rn.f32x2 / add.rn.f32x2: 2 IEEE-RN fp32 ops per issue slot
//   - set.gt.f32.f32: spike as 1.0f/0.0f in one instruction (no FSETP+SEL)
//   - reset subtract as fmaf(s,-1,m): FFMA-imm (rt=1), == __fsub_rn(m,s) for s in {0,1}
// Evaluation order preserved exactly: ((0.9*m) + cur) - reset, then compare >1.

#define SNN_T 20
#define SNN_H 4

union F2 { float2 f; unsigned long long u; };

__device__ __forceinline__ void mul2(F2& d, const F2& a, const F2& b) {
    asm("mul.rn.f32x2 %0, %1, %2;" : "=l"(d.u) : "l"(a.u), "l"(b.u));
}
__device__ __forceinline__ void add2(F2& d, const F2& a, const F2& b) {
    asm("add.rn.f32x2 %0, %1, %2;" : "=l"(d.u) : "l"(a.u), "l"(b.u));
}
// 1.0f if a > b else 0.0f, single SASS FSET
__device__ __forceinline__ float fset_gt(float a, float b) {
    float r;
    asm("set.gt.f32.f32 %0, %1, %2;" : "=f"(r) : "f"(a), "f"(b));
    return r;
}

__global__ __launch_bounds__(256) void xornet_snn_kernel(
    const float* __restrict__ x,    // [B, 2]
    const float* __restrict__ w1,   // [4, 2]
    const float* __restrict__ w2,   // [1, 4]
    float* __restrict__ out,        // [T, B, 1]
    int B)
{
    const int i = blockIdx.x * blockDim.x + threadIdx.x;  // handles b = 4i..4i+3
    if (i * 4 >= B) return;
    const int Bq = B >> 2;

    // Broadcast weights (L2/L1 hit after first warp).
    float w1r0[SNN_H], w1r1[SNN_H], w2r[SNN_H];
#pragma unroll
    for (int h = 0; h < SNN_H; h++) {
        w1r0[h] = __ldg(&w1[2 * h]);
        w1r1[h] = __ldg(&w1[2 * h + 1]);
        w2r[h]  = __ldg(&w2[h]);
    }

    // x for 4 batch elements: 2x float4.
    const float4 xa = __ldg(&((const float4*)x)[2 * i]);
    const float4 xb = __ldg(&((const float4*)x)[2 * i + 1]);
    const float x0[4] = {xa.x, xa.z, xb.x, xb.z};
    const float x1[4] = {xa.y, xa.w, xb.y, xb.w};

    // cur[l][p] packs neurons (2p, 2p+1); k-ascending fma dot, same as R2.
    F2 cur[4][2];
#pragma unroll
    for (int l = 0; l < 4; l++)
#pragma unroll
        for (int p = 0; p < 2; p++) {
            cur[l][p].f.x = fmaf(x1[l], w1r1[2 * p],     __fmul_rn(x0[l], w1r0[2 * p]));
            cur[l][p].f.y = fmaf(x1[l], w1r1[2 * p + 1], __fmul_rn(x0[l], w1r0[2 * p + 1]));
        }

    F2 c09; c09.f = make_float2(0.9f, 0.9f);

    // State: packed membranes, spikes as 1.0/0.0 floats.
    F2 m1[4][2];      // layer-1 membranes, 16 neurons
    float s1[4][SNN_H];
    F2 m2p[2];        // layer-2 membranes, lanes (0,1) and (2,3)
    float s2[4];
#pragma unroll
    for (int l = 0; l < 4; l++) {
        s2[l] = 0.0f;
#pragma unroll
        for (int p = 0; p < 2; p++) { m1[l][p].u = 0ull; }
#pragma unroll
        for (int h = 0; h < SNN_H; h++) s1[l][h] = 0.0f;
    }
    m2p[0].u = 0ull; m2p[1].u = 0ull;

#pragma unroll
    for (int t = 0; t < SNN_T; t++) {
        float o[4];
#pragma unroll
        for (int l = 0; l < 4; l++) {
#pragma unroll
            for (int p = 0; p < 2; p++) {
                F2 mm;
                mul2(mm, m1[l][p], c09);           // 0.9*m   (packed, RN)
                add2(mm, mm, cur[l][p]);           // + cur   (packed, RN)
                // - reset (prev spike), FFMA-imm == __fsub_rn(m, s) for s in {0,1}
                mm.f.x = fmaf(s1[l][2 * p],     -1.0f, mm.f.x);
                mm.f.y = fmaf(s1[l][2 * p + 1], -1.0f, mm.f.y);
                m1[l][p] = mm;
                // spike = (m > 1) as 1.0f/0.0f, single FSET
                s1[l][2 * p]     = fset_gt(mm.f.x, 1.0f);
                s1[l][2 * p + 1] = fset_gt(mm.f.y, 1.0f);
            }
            // spk1 @ w2^T: binary s -> products exact; same rounding chain as
            // XLA's k-ascending fma dot (first term = exact mul).
            float oo = __fmul_rn(s1[l][0], w2r[0]);
            oo = fmaf(s1[l][1], w2r[1], oo);
            oo = fmaf(s1[l][2], w2r[2], oo);
            oo = fmaf(s1[l][3], w2r[3], oo);
            o[l] = oo;
        }
        // layer-2 LIF, packed across batch-lane pairs
#pragma unroll
        for (int q = 0; q < 2; q++) {
            F2 op; op.f = make_float2(o[2 * q], o[2 * q + 1]);
            F2 mm;
            mul2(mm, m2p[q], c09);
            add2(mm, mm, op);
            mm.f.x = fmaf(s2[2 * q],     -1.0f, mm.f.x);
            mm.f.y = fmaf(s2[2 * q + 1], -1.0f, mm.f.y);
            m2p[q] = mm;
            s2[2 * q]     = fset_gt(mm.f.x, 1.0f);
            s2[2 * q + 1] = fset_gt(mm.f.y, 1.0f);
        }
        float4 ov;
        ov.x = s2[0]; ov.y = s2[1]; ov.z = s2[2]; ov.w = s2[3];
        ((float4*)out)[(size_t)t * Bq + i] = ov;   // warp-coalesced STG.128
    }
}

extern "C" void kernel_launch(void* const* d_in, const int* in_sizes, int n_in,
                              void* d_out, int out_size)
{
    const float* x  = (const float*)d_in[0];   // [B, 2]
    const float* w1 = (const float*)d_in[1];   // [4, 2]
    const float* w2 = (const float*)d_in[2];   // [1, 4]
    float* out = (float*)d_out;                // [T, B, 1]

    const int B = in_sizes[0] / 2;             // 1,048,576
    const int threads = 256;
    const int nthreads = B / 4;
    const int blocks = (nthreads + threads - 1) / threads;

    xornet_snn_kernel<<<blocks, threads>>>(x, w1, w2, out, B);
}